// round 12
// baseline (speedup 1.0000x reference)
#include <cuda_runtime.h>

// QuantumAutoencoder strip-pool + cos. In: [32768,3,32,32] f32 -> Out: [32768,64] f32.
// TERMINAL kernel: flat grid, 2 imgs/block, 256 thr, regs 32, streaming hints.
//
// Layout insight: reference's reshape(B,3,8,8,4,4).mean((-1,-2)) pools 16
// CONTIGUOUS floats per patch (strip pooling). float4-slot t (0..255) is the
// same spatial position across the 3 channels (offsets t, t+256, t+512 in
// float4 units), so each thread directly accumulates its 3-channel partial;
// warp loads are 512B fully-contiguous. Patch p = slots 4p..4p+3 -> 2-step
// shfl_xor reduce; lane (t&3)==0 stores (8 consecutive floats per warp).
//
// Perf status: at the B300 path-independent LTS throughput cap. Identical SASS
// measured 60.16-61.31us kernel / 6698-6823 GB/s across runs vs ~60.7us traffic
// floor (410 MB). Explored and rejected: MLP-12 (occupancy collapse), persistent
// grid (loop-carried MLP collapse), 512-thr blocks (neutral), vector-store
// epilogue (neutral). No remaining theory predicts improvement.

#define PI_F 3.14159265358979323846f
#define IMGS_PER_BLOCK 2

__global__ void __launch_bounds__(256) qae_kernel(const float4* __restrict__ in,
                                                  float* __restrict__ out) {
    int t = threadIdx.x;                       // 0..255
    int img0 = blockIdx.x * IMGS_PER_BLOCK;

    float s[IMGS_PER_BLOCK];
    #pragma unroll
    for (int i = 0; i < IMGS_PER_BLOCK; ++i) {
        const float4* p = in + (size_t)(img0 + i) * 768;  // 3*1024/4
        float4 a = __ldcs(p + t);
        float4 b = __ldcs(p + t + 256);
        float4 c = __ldcs(p + t + 512);
        s[i] = ((a.x + a.y) + (a.z + a.w))
             + ((b.x + b.y) + (b.z + b.w))
             + ((c.x + c.y) + (c.z + c.w));
    }

    #pragma unroll
    for (int i = 0; i < IMGS_PER_BLOCK; ++i) {
        float v = s[i];
        v += __shfl_xor_sync(0xffffffffu, v, 1);
        v += __shfl_xor_sync(0xffffffffu, v, 2);
        if ((t & 3) == 0) {
            float mean = v * (1.0f / 48.0f);
            float ang = mean * (PI_F / 255.0f) - (PI_F * 0.5f);
            __stcs(&out[(size_t)(img0 + i) * 64 + (t >> 2)], cosf(ang));
        }
    }
}

extern "C" void kernel_launch(void* const* d_in, const int* in_sizes, int n_in,
                              void* d_out, int out_size) {
    const float4* in = (const float4*)d_in[0];
    float* out = (float*)d_out;
    int n_img = in_sizes[0] / (3 * 32 * 32);     // 32768
    int blocks = n_img / IMGS_PER_BLOCK;         // 16384
    qae_kernel<<<blocks, 256>>>(in, out);
}

// round 13
// speedup vs baseline: 1.0388x; 1.0388x over previous
#include <cuda_runtime.h>

// QuantumAutoencoder strip-pool + cos. In: [32768,3,32,32] f32 -> Out: [32768,64] f32.
// TERMINAL kernel: flat grid, 2 imgs/block, 256 thr, regs 32, streaming hints.
//
// Layout insight: reference's reshape(B,3,8,8,4,4).mean((-1,-2)) pools 16
// CONTIGUOUS floats per patch (strip pooling). float4-slot t (0..255) is the
// same spatial position across the 3 channels (offsets t, t+256, t+512 in
// float4 units), so each thread directly accumulates its 3-channel partial;
// warp loads are 512B fully-contiguous. Patch p = slots 4p..4p+3 -> 2-step
// shfl_xor reduce; lane (t&3)==0 stores (8 consecutive floats per warp).
//
// Perf status: at the B300 path-independent LTS throughput cap. This exact
// SASS measured 60.16 / 61.25 / 62.46 us kernel (6572-6823 GB/s) across three
// runs vs ~60.7us traffic floor (410 MB single-touch) — run-to-run DVFS/L2
// variance, not kernel-controllable. Explored and rejected: MLP-12 (occupancy
// collapse), persistent grid (loop-carried MLP collapse), 512-thr blocks
// (neutral), vector-store epilogue (neutral).

#define PI_F 3.14159265358979323846f
#define IMGS_PER_BLOCK 2

__global__ void __launch_bounds__(256) qae_kernel(const float4* __restrict__ in,
                                                  float* __restrict__ out) {
    int t = threadIdx.x;                       // 0..255
    int img0 = blockIdx.x * IMGS_PER_BLOCK;

    float s[IMGS_PER_BLOCK];
    #pragma unroll
    for (int i = 0; i < IMGS_PER_BLOCK; ++i) {
        const float4* p = in + (size_t)(img0 + i) * 768;  // 3*1024/4
        float4 a = __ldcs(p + t);
        float4 b = __ldcs(p + t + 256);
        float4 c = __ldcs(p + t + 512);
        s[i] = ((a.x + a.y) + (a.z + a.w))
             + ((b.x + b.y) + (b.z + b.w))
             + ((c.x + c.y) + (c.z + c.w));
    }

    #pragma unroll
    for (int i = 0; i < IMGS_PER_BLOCK; ++i) {
        float v = s[i];
        v += __shfl_xor_sync(0xffffffffu, v, 1);
        v += __shfl_xor_sync(0xffffffffu, v, 2);
        if ((t & 3) == 0) {
            float mean = v * (1.0f / 48.0f);
            float ang = mean * (PI_F / 255.0f) - (PI_F * 0.5f);
            __stcs(&out[(size_t)(img0 + i) * 64 + (t >> 2)], cosf(ang));
        }
    }
}

extern "C" void kernel_launch(void* const* d_in, const int* in_sizes, int n_in,
                              void* d_out, int out_size) {
    const float4* in = (const float4*)d_in[0];
    float* out = (float*)d_out;
    int n_img = in_sizes[0] / (3 * 32 * 32);     // 32768
    int blocks = n_img / IMGS_PER_BLOCK;         // 16384
    qae_kernel<<<blocks, 256>>>(in, out);
}